// round 17
// baseline (speedup 1.0000x reference)
#include <cuda_runtime.h>
#include <cuda_fp16.h>
#include <math.h>
#include <stdint.h>

// Problem constants
#define B_  32
#define C_  512
#define M_  784            // 28*28
#define MPAD 800           // padded K for fp16 split x (25 chunks of 32)
#define NSQ (C_*C_)        // 262144
#define TOT ((long)B_*NSQ)

// ---------------- scratch ----------------
__device__ __half g_xh [B_*C_*MPAD]; // x hi halves (zero-padded)
__device__ __half g_xl [B_*C_*MPAD]; // x lo halves
__device__ __half g_Th [B_*NSQ];     // T = cov/trace in fp16
__device__ __half g_P2 [B_*NSQ];     // scratch squares
__device__ __half g_S1h[B_*NSQ];
__device__ __half g_S2h[B_*NSQ];
__device__ float  g_mean[B_*C_];
__device__ float  g_ssq [B_*C_];     // per-row sum of squares
__device__ float  g_itr[B_];
__device__ float  g_str[B_];
__device__ float  g_cs [B_*C_];

__device__ __forceinline__ void mma_f16(float* c, const uint32_t* a, const uint32_t* b) {
    asm volatile("mma.sync.aligned.m16n8k16.row.col.f32.f16.f16.f32 "
        "{%0,%1,%2,%3}, {%4,%5,%6,%7}, {%8,%9}, {%0,%1,%2,%3};"
        : "+f"(c[0]), "+f"(c[1]), "+f"(c[2]), "+f"(c[3])
        : "r"(a[0]), "r"(a[1]), "r"(a[2]), "r"(a[3]), "r"(b[0]), "r"(b[1]));
}

__constant__ int c_bi[10] = {0,0,0,0,1,1,1,2,2,3};
__constant__ int c_bj[10] = {0,1,2,3,1,2,3,2,3,3};

// ================= split x into fp16 hi/lo (padded) =================
__global__ void splitx_kernel(const float* __restrict__ x,
                              __half* __restrict__ xh, __half* __restrict__ xl)
{
    long g = (long)blockIdx.x * blockDim.x + threadIdx.x;   // one uint4 (8 halfs)
    const long total = (long)B_ * C_ * (MPAD / 8);
    if (g >= total) return;
    long row = g / (MPAD / 8);
    int grp = (int)(g % (MPAD / 8));
    __half hi[8], lo[8];
    if (grp < 98) {   // groups 0..97 are fully inside M_=784
        const float* src = x + row * M_ + grp * 8;
        #pragma unroll
        for (int e = 0; e < 8; e++) {
            float v = src[e];
            __half h = __float2half_rn(v);
            hi[e] = h;
            lo[e] = __float2half_rn(v - __half2float(h));
        }
    } else {
        #pragma unroll
        for (int e = 0; e < 8; e++) { hi[e] = __float2half_rn(0.f); lo[e] = hi[e]; }
    }
    *(uint4*)(xh + row * MPAD + grp * 8) = *(uint4*)hi;
    *(uint4*)(xl + row * MPAD + grp * 8) = *(uint4*)lo;
}

// ================= per-row mean and sum-of-squares =================
__global__ void mean_kernel(const float* __restrict__ x, float* __restrict__ mean,
                            float* __restrict__ ssq)
{
    int warp = (blockIdx.x * blockDim.x + threadIdx.x) >> 5;
    int lane = threadIdx.x & 31;
    if (warp >= B_*C_) return;
    const float* row = x + (long)warp * M_;
    float s = 0.f, q = 0.f;
    for (int k = lane; k < M_; k += 32) { float v = row[k]; s += v; q = fmaf(v, v, q); }
    #pragma unroll
    for (int off = 16; off; off >>= 1) {
        s += __shfl_down_sync(0xffffffffu, s, off);
        q += __shfl_down_sync(0xffffffffu, q, off);
    }
    if (lane == 0) { mean[warp] = s * (1.0f / M_); ssq[warp] = q; }
}

// ================= trace from mean/ssq (before cov GEMM) =================
__global__ void tracex_kernel(const float* __restrict__ mean, const float* __restrict__ ssq,
                              float* __restrict__ itr, float* __restrict__ str)
{
    __shared__ float sh[512];
    const int b = blockIdx.x;
    const int i = threadIdx.x;
    float m = mean[b * C_ + i];
    sh[i] = ssq[b * C_ + i] * (1.0f / M_) - m * m;
    __syncthreads();
    for (int off = 256; off; off >>= 1) {
        if (i < off) sh[i] += sh[i + off];
        __syncthreads();
    }
    if (i == 0) { float t = sh[0]; itr[b] = 1.0f / t; str[b] = sqrtf(t); }
}

// ================= cov GEMM in split-fp16: T = ((x x^T)/M - mean mean^T) * itr ==========
#define HPAD 40
#define HT (128*HPAD)
#define HSTG (4*HT)
#define COV_SMEM (2*HSTG*2)           // 81920 bytes

__global__ void __launch_bounds__(256, 2)
cov_gemm_h(const __half* __restrict__ xhg, const __half* __restrict__ xlg,
           __half* __restrict__ Tg, const float* __restrict__ meang,
           const float* __restrict__ itrg)
{
    extern __shared__ __half smh[];
    const int tid = threadIdx.x;
    const int b = blockIdx.z;
    const __half* XH = xhg + (long)b * C_ * MPAD;
    const __half* XL = xlg + (long)b * C_ * MPAD;
    const int ib = c_bi[blockIdx.x] * 128;
    const int jb = c_bj[blockIdx.x] * 128;
    const float covInvM = 1.0f / M_;
    const float itr = itrg[b];

    const int wid = tid >> 5, lane = tid & 31;
    const int wm = wid & 1, wn = wid >> 1;
    const int gid = lane >> 2, tig = lane & 3;

    float acc[4][4][4];
    #pragma unroll
    for (int mf = 0; mf < 4; mf++)
        #pragma unroll
        for (int nf = 0; nf < 4; nf++)
            #pragma unroll
            for (int e = 0; e < 4; e++) acc[mf][nf][e] = 0.f;

    uint4 rah[2], ral[2], rbh[2], rbl[2];
    #pragma unroll
    for (int q = 0; q < 2; q++) {
        int u = tid + q * 256; int r = u >> 2; int seg = u & 3;
        rah[q] = *(const uint4*)(XH + (long)(ib + r) * MPAD + seg * 8);
        ral[q] = *(const uint4*)(XL + (long)(ib + r) * MPAD + seg * 8);
        rbh[q] = *(const uint4*)(XH + (long)(jb + r) * MPAD + seg * 8);
        rbl[q] = *(const uint4*)(XL + (long)(jb + r) * MPAD + seg * 8);
    }
    #pragma unroll
    for (int q = 0; q < 2; q++) {
        int u = tid + q * 256; int r = u >> 2; int seg = u & 3;
        *(uint4*)(smh + 0*HT + (long)r * HPAD + seg * 8) = rah[q];
        *(uint4*)(smh + 1*HT + (long)r * HPAD + seg * 8) = ral[q];
        *(uint4*)(smh + 2*HT + (long)r * HPAD + seg * 8) = rbh[q];
        *(uint4*)(smh + 3*HT + (long)r * HPAD + seg * 8) = rbl[q];
    }
    __syncthreads();

    const int NCH = MPAD / 32;   // 25 chunks
    for (int i = 0; i < NCH; i++) {
        if (i + 1 < NCH) {
            const int k0 = (i + 1) * 32;
            #pragma unroll
            for (int q = 0; q < 2; q++) {
                int u = tid + q * 256; int r = u >> 2; int seg = u & 3;
                rah[q] = *(const uint4*)(XH + (long)(ib + r) * MPAD + k0 + seg * 8);
                ral[q] = *(const uint4*)(XL + (long)(ib + r) * MPAD + k0 + seg * 8);
                rbh[q] = *(const uint4*)(XH + (long)(jb + r) * MPAD + k0 + seg * 8);
                rbl[q] = *(const uint4*)(XL + (long)(jb + r) * MPAD + k0 + seg * 8);
            }
        }
        const __half* S = smh + (i & 1) * HSTG;
        #pragma unroll
        for (int ks = 0; ks < 2; ks++) {
            uint32_t ah[4][4], al[4][4];
            #pragma unroll
            for (int mf = 0; mf < 4; mf++) {
                long off = (long)(wm * 64 + mf * 16 + gid) * HPAD + ks * 16 + tig * 2;
                const __half* ph = S + 0*HT + off;
                const __half* pl = S + 1*HT + off;
                ah[mf][0] = *(const uint32_t*)ph;
                ah[mf][1] = *(const uint32_t*)(ph + 8 * HPAD);
                ah[mf][2] = *(const uint32_t*)(ph + 8);
                ah[mf][3] = *(const uint32_t*)(ph + 8 * HPAD + 8);
                al[mf][0] = *(const uint32_t*)pl;
                al[mf][1] = *(const uint32_t*)(pl + 8 * HPAD);
                al[mf][2] = *(const uint32_t*)(pl + 8);
                al[mf][3] = *(const uint32_t*)(pl + 8 * HPAD + 8);
            }
            uint32_t bh[4][2], bl[4][2];
            #pragma unroll
            for (int nf = 0; nf < 4; nf++) {
                long off = (long)(wn * 32 + nf * 8 + gid) * HPAD + ks * 16 + tig * 2;
                const __half* ph = S + 2*HT + off;
                const __half* pl = S + 3*HT + off;
                bh[nf][0] = *(const uint32_t*)ph;
                bh[nf][1] = *(const uint32_t*)(ph + 8);
                bl[nf][0] = *(const uint32_t*)pl;
                bl[nf][1] = *(const uint32_t*)(pl + 8);
            }
            #pragma unroll
            for (int mf = 0; mf < 4; mf++)
                #pragma unroll
                for (int nf = 0; nf < 4; nf++) {
                    mma_f16(acc[mf][nf], ah[mf], bh[nf]);
                    mma_f16(acc[mf][nf], ah[mf], bl[nf]);
                    mma_f16(acc[mf][nf], al[mf], bh[nf]);
                }
        }
        if (i + 1 < NCH) {
            __half* D = smh + ((i + 1) & 1) * HSTG;
            #pragma unroll
            for (int q = 0; q < 2; q++) {
                int u = tid + q * 256; int r = u >> 2; int seg = u & 3;
                *(uint4*)(D + 0*HT + (long)r * HPAD + seg * 8) = rah[q];
                *(uint4*)(D + 1*HT + (long)r * HPAD + seg * 8) = ral[q];
                *(uint4*)(D + 2*HT + (long)r * HPAD + seg * 8) = rbh[q];
                *(uint4*)(D + 3*HT + (long)r * HPAD + seg * 8) = rbl[q];
            }
        }
        __syncthreads();
    }

    __half* T = Tg + (long)b * NSQ;
    const bool offdiag = (ib != jb);
    #pragma unroll
    for (int mf = 0; mf < 4; mf++) {
        const int r0 = ib + wm * 64 + mf * 16 + gid;
        float mi0 = meang[b * C_ + r0];
        float mi1 = meang[b * C_ + r0 + 8];
        #pragma unroll
        for (int nf = 0; nf < 4; nf++) {
            const int c0 = jb + wn * 32 + nf * 8 + tig * 2;
            float mj0 = meang[b * C_ + c0], mj1 = meang[b * C_ + c0 + 1];
            float t0 = (acc[mf][nf][0] * covInvM - mi0 * mj0) * itr;
            float t1 = (acc[mf][nf][1] * covInvM - mi0 * mj1) * itr;
            float t2 = (acc[mf][nf][2] * covInvM - mi1 * mj0) * itr;
            float t3 = (acc[mf][nf][3] * covInvM - mi1 * mj1) * itr;
            __half h0 = __float2half_rn(t0), h1 = __float2half_rn(t1);
            __half h2 = __float2half_rn(t2), h3 = __float2half_rn(t3);
            *(__half2*)(T + (long)r0 * C_ + c0)       = __halves2half2(h0, h1);
            *(__half2*)(T + (long)(r0 + 8) * C_ + c0) = __halves2half2(h2, h3);
            if (offdiag) {
                T[(long)c0 * C_ + r0]           = h0;
                T[(long)(c0 + 1) * C_ + r0]     = h1;
                T[(long)c0 * C_ + r0 + 8]       = h2;
                T[(long)(c0 + 1) * C_ + r0 + 8] = h3;
            }
        }
    }
}

// ================= fp16 power GEMM: D = P * Q^T (symmetric, upper-tri tiles) ============
#define PPAD 40
#define PT_H (128*PPAD)
#define PSTG (2*PT_H)
#define POW_SMEM (2*PSTG*2)

template<int MODE>
__global__ void __launch_bounds__(256, 2)
pow_gemm(const __half* __restrict__ Pg, const __half* __restrict__ Qg,
         __half* __restrict__ Dg,
         const __half* __restrict__ T1g, const __half* __restrict__ T2g)
{
    extern __shared__ __half smh[];
    const int tid = threadIdx.x;
    const int b = blockIdx.z;
    const __half* P = Pg + (long)b * NSQ;
    const __half* Q = Qg + (long)b * NSQ;
    const int ib = c_bi[blockIdx.x] * 128;
    const int jb = c_bj[blockIdx.x] * 128;

    const int wid = tid >> 5, lane = tid & 31;
    const int wm = wid & 1, wn = wid >> 1;
    const int gid = lane >> 2, tig = lane & 3;

    float acc[4][4][4];
    #pragma unroll
    for (int mf = 0; mf < 4; mf++)
        #pragma unroll
        for (int nf = 0; nf < 4; nf++)
            #pragma unroll
            for (int e = 0; e < 4; e++) acc[mf][nf][e] = 0.f;

    uint4 ra[2], rb[2];
    #pragma unroll
    for (int q = 0; q < 2; q++) {
        int u = tid + q * 256; int r = u >> 2; int seg = u & 3;
        ra[q] = *(const uint4*)(P + (long)(ib + r) * C_ + seg * 8);
        rb[q] = *(const uint4*)(Q + (long)(jb + r) * C_ + seg * 8);
    }
    #pragma unroll
    for (int q = 0; q < 2; q++) {
        int u = tid + q * 256; int r = u >> 2; int seg = u & 3;
        *(uint4*)(smh + (long)r * PPAD + seg * 8)        = ra[q];
        *(uint4*)(smh + PT_H + (long)r * PPAD + seg * 8) = rb[q];
    }
    __syncthreads();

    for (int i = 0; i < 16; i++) {
        if (i + 1 < 16) {
            const int k0 = (i + 1) * 32;
            #pragma unroll
            for (int q = 0; q < 2; q++) {
                int u = tid + q * 256; int r = u >> 2; int seg = u & 3;
                ra[q] = *(const uint4*)(P + (long)(ib + r) * C_ + k0 + seg * 8);
                rb[q] = *(const uint4*)(Q + (long)(jb + r) * C_ + k0 + seg * 8);
            }
        }
        const __half* As = smh + (i & 1) * PSTG;
        const __half* Bs = As + PT_H;
        #pragma unroll
        for (int ks = 0; ks < 2; ks++) {
            uint32_t ah[4][4];
            #pragma unroll
            for (int mf = 0; mf < 4; mf++) {
                const __half* ap = As + (long)(wm * 64 + mf * 16 + gid) * PPAD + ks * 16 + tig * 2;
                ah[mf][0] = *(const uint32_t*)ap;
                ah[mf][1] = *(const uint32_t*)(ap + 8 * PPAD);
                ah[mf][2] = *(const uint32_t*)(ap + 8);
                ah[mf][3] = *(const uint32_t*)(ap + 8 * PPAD + 8);
            }
            uint32_t bf[4][2];
            #pragma unroll
            for (int nf = 0; nf < 4; nf++) {
                const __half* bp = Bs + (long)(wn * 32 + nf * 8 + gid) * PPAD + ks * 16 + tig * 2;
                bf[nf][0] = *(const uint32_t*)bp;
                bf[nf][1] = *(const uint32_t*)(bp + 8);
            }
            #pragma unroll
            for (int mf = 0; mf < 4; mf++)
                #pragma unroll
                for (int nf = 0; nf < 4; nf++)
                    mma_f16(acc[mf][nf], ah[mf], bf[nf]);
        }
        if (i + 1 < 16) {
            __half* Ad = smh + ((i + 1) & 1) * PSTG;
            #pragma unroll
            for (int q = 0; q < 2; q++) {
                int u = tid + q * 256; int r = u >> 2; int seg = u & 3;
                *(uint4*)(Ad + (long)r * PPAD + seg * 8)        = ra[q];
                *(uint4*)(Ad + PT_H + (long)r * PPAD + seg * 8) = rb[q];
            }
        }
        __syncthreads();
    }

    __half* D = Dg + (long)b * NSQ;
    const __half* T1 = T1g + (long)b * NSQ;
    const __half* T2 = T2g + (long)b * NSQ;
    const bool offdiag = (ib != jb);
    #pragma unroll
    for (int mf = 0; mf < 4; mf++) {
        const int r0 = ib + wm * 64 + mf * 16 + gid;
        #pragma unroll
        for (int nf = 0; nf < 4; nf++) {
            const int c0 = jb + wn * 32 + nf * 8 + tig * 2;
            float v0, v1, v2, v3;
            if (MODE == 0) {
                v0 = acc[mf][nf][0]; v1 = acc[mf][nf][1];
                v2 = acc[mf][nf][2]; v3 = acc[mf][nf][3];
            } else {
                float2 t1a = __half22float2(*(const __half2*)(T1 + (long)r0 * C_ + c0));
                float2 t2a = __half22float2(*(const __half2*)(T2 + (long)r0 * C_ + c0));
                float2 t1b = __half22float2(*(const __half2*)(T1 + (long)(r0 + 8) * C_ + c0));
                float2 t2b = __half22float2(*(const __half2*)(T2 + (long)(r0 + 8) * C_ + c0));
                v0 = 2.25f * t1a.x - 1.5f * t2a.x + 0.25f * acc[mf][nf][0];
                v1 = 2.25f * t1a.y - 1.5f * t2a.y + 0.25f * acc[mf][nf][1];
                v2 = 2.25f * t1b.x - 1.5f * t2b.x + 0.25f * acc[mf][nf][2];
                v3 = 2.25f * t1b.y - 1.5f * t2b.y + 0.25f * acc[mf][nf][3];
            }
            __half h0 = __float2half_rn(v0), h1 = __float2half_rn(v1);
            __half h2 = __float2half_rn(v2), h3 = __float2half_rn(v3);
            *(__half2*)(D + (long)r0 * C_ + c0)       = __halves2half2(h0, h1);
            *(__half2*)(D + (long)(r0 + 8) * C_ + c0) = __halves2half2(h2, h3);
            if (offdiag) {
                D[(long)c0 * C_ + r0]           = h0;
                D[(long)(c0 + 1) * C_ + r0]     = h1;
                D[(long)c0 * C_ + r0 + 8]       = h2;
                D[(long)(c0 + 1) * C_ + r0 + 8] = h3;
            }
        }
    }
}

// ================= Newton-Schulz vector chain: 16 matvecs =================
struct ChainCtx {
    const __half* S2;
    float* v;
    float* partial;
    float* pool;
    int    tid;
};

__device__ void mv(const __half* Ab, float* v, float* partial, int tid)
{
    const int cg = tid & 63;
    const int rg = tid >> 6;
    const __half* base = Ab + (long)rg * 64 * C_ + cg * 8;
    const float* vs = v + rg * 64;

    float a0 = 0.f, a1 = 0.f, a2 = 0.f, a3 = 0.f;
    float a4 = 0.f, a5 = 0.f, a6 = 0.f, a7 = 0.f;
    #pragma unroll 8
    for (int r = 0; r < 64; r++) {
        uint4 q = *(const uint4*)(base + (long)r * C_);
        float s = vs[r];
        float2 f0 = __half22float2(*(__half2*)&q.x);
        float2 f1 = __half22float2(*(__half2*)&q.y);
        float2 f2 = __half22float2(*(__half2*)&q.z);
        float2 f3 = __half22float2(*(__half2*)&q.w);
        a0 = fmaf(s, f0.x, a0);
        a1 = fmaf(s, f0.y, a1);
        a2 = fmaf(s, f1.x, a2);
        a3 = fmaf(s, f1.y, a3);
        a4 = fmaf(s, f2.x, a4);
        a5 = fmaf(s, f2.y, a5);
        a6 = fmaf(s, f3.x, a6);
        a7 = fmaf(s, f3.y, a7);
    }
    *(float4*)(partial + rg * 512 + cg * 8)     = make_float4(a0, a1, a2, a3);
    *(float4*)(partial + rg * 512 + cg * 8 + 4) = make_float4(a4, a5, a6, a7);
    __syncthreads();
    float sum = 0.f;
    #pragma unroll
    for (int g = 0; g < 8; g++) sum += partial[g * 512 + tid];
    v[tid] = sum;
    __syncthreads();
}

__device__ void applyW_direct(const __half* Ab, float* v, float* partial,
                              float* save, int tid)
{
    save[tid] = v[tid];
    __syncthreads();
    mv(Ab, v, partial, tid);
    float nv = 1.5f * save[tid] - 0.5f * v[tid];
    __syncthreads();
    v[tid] = nv;
    __syncthreads();
}

__device__ void exec_W(int k0, ChainCtx& c)
{
    int ty[16], kk[16], sp[16], st[16];
    int top = 0;
    ty[0] = 0; kk[0] = k0; sp[0] = 0; st[0] = 0; top = 1;
    while (top > 0) {
        const int i = top - 1;
        if (ty[i] == 0) {
            if (st[i] == 0) {
                float* save = c.pool + sp[i] * 512;
                save[c.tid] = c.v[c.tid];
                __syncthreads();
                st[i] = 1;
                ty[top] = 1; kk[top] = kk[i]; sp[top] = sp[i] + 1; st[top] = 0; top++;
            } else {
                float* save = c.pool + sp[i] * 512;
                float nv = 1.5f * save[c.tid] - 0.5f * c.v[c.tid];
                __syncthreads();
                c.v[c.tid] = nv;
                __syncthreads();
                top--;
            }
        } else {
            if (kk[i] == 2) { mv(c.S2, c.v, c.partial, c.tid); top--; }
            else if (st[i] == 0) {
                st[i] = 1;
                ty[top] = 1; kk[top] = kk[i] - 1; sp[top] = sp[i]; st[top] = 0; top++;
            } else if (st[i] == 1) {
                st[i] = 2;
                ty[top] = 0; kk[top] = kk[i] - 1; sp[top] = sp[i]; st[top] = 0; top++;
            } else if (st[i] == 2) {
                st[i] = 3;
                ty[top] = 0; kk[top] = kk[i] - 1; sp[top] = sp[i]; st[top] = 0; top++;
            } else top--;
        }
    }
}

__global__ void __launch_bounds__(512, 1)
chain_kernel(const __half* __restrict__ Th, const __half* __restrict__ S1h,
             const __half* __restrict__ S2h,
             const float* __restrict__ str, float* __restrict__ cs)
{
    __shared__ float v[512];
    __shared__ float partial[8 * 512];
    __shared__ float pool[5 * 512];
    const int b = blockIdx.x;
    const int tid = threadIdx.x;

    const __half* T  = Th  + (long)b * NSQ;
    const __half* S1 = S1h + (long)b * NSQ;

    ChainCtx c;
    c.S2 = S2h + (long)b * NSQ;
    c.v = v; c.partial = partial; c.pool = pool;
    c.tid = tid;

    v[tid] = 1.0f;
    __syncthreads();

    mv(T, v, partial, tid);
    applyW_direct(T,  v, partial, pool, tid);
    applyW_direct(S1, v, partial, pool, tid);
    for (int k = 2; k <= 4; k++)
        exec_W(k, c);

    cs[b * C_ + tid] = v[tid] * str[b] * (1.0f / C_);
}

// ---------------- out = cov_sum * x ----------------
__global__ void scale_kernel(const float* __restrict__ x,
                             const float* __restrict__ cs, float* __restrict__ out)
{
    long i4 = (long)blockIdx.x * blockDim.x + threadIdx.x;
    const long total4 = (long)B_ * C_ * M_ / 4;
    if (i4 >= total4) return;
    long e = i4 * 4;
    int bc = (int)(e / M_);
    float s = cs[bc];
    float4 v = *(const float4*)(x + e);
    v.x *= s; v.y *= s; v.z *= s; v.w *= s;
    *(float4*)(out + e) = v;
}

// ---------------- launcher ----------------
extern "C" void kernel_launch(void* const* d_in, const int* in_sizes, int n_in,
                              void* d_out, int out_size)
{
    const float* x = (const float*)d_in[0];
    float* out = (float*)d_out;

    float *mean, *ssq, *itr, *str, *cs;
    __half *xh, *xl, *Th, *P2, *S1h, *S2h;
    cudaGetSymbolAddress((void**)&xh,   g_xh);
    cudaGetSymbolAddress((void**)&xl,   g_xl);
    cudaGetSymbolAddress((void**)&Th,   g_Th);
    cudaGetSymbolAddress((void**)&P2,   g_P2);
    cudaGetSymbolAddress((void**)&S1h,  g_S1h);
    cudaGetSymbolAddress((void**)&S2h,  g_S2h);
    cudaGetSymbolAddress((void**)&mean, g_mean);
    cudaGetSymbolAddress((void**)&ssq,  g_ssq);
    cudaGetSymbolAddress((void**)&itr,  g_itr);
    cudaGetSymbolAddress((void**)&str,  g_str);
    cudaGetSymbolAddress((void**)&cs,   g_cs);

    cudaFuncSetAttribute(cov_gemm_h, cudaFuncAttributeMaxDynamicSharedMemorySize, COV_SMEM);
    cudaFuncSetAttribute(pow_gemm<0>, cudaFuncAttributeMaxDynamicSharedMemorySize, POW_SMEM);
    cudaFuncSetAttribute(pow_gemm<1>, cudaFuncAttributeMaxDynamicSharedMemorySize, POW_SMEM);

    // 1) split x into fp16 hi/lo ; row means + sum-of-squares
    const long ng = (long)B_ * C_ * (MPAD / 8);
    splitx_kernel<<<(int)((ng + 255) / 256), 256>>>(x, xh, xl);
    mean_kernel<<<(B_*C_ + 7) / 8, 256>>>(x, mean, ssq);

    // 2) trace from mean/ssq (before the GEMM)
    tracex_kernel<<<B_, 512>>>(mean, ssq, itr, str);

    // 3) T directly in fp16 via split-fp16 HMMA (upper-tri + mirror)
    cov_gemm_h<<<dim3(10, 1, B_), 256, COV_SMEM>>>(xh, xl, Th, mean, itr);

    // 4) S1 = cubic(T) ; S2 = cubic(S1)   (symmetric tiles)
    const dim3 pg(10, 1, B_);
    pow_gemm<0><<<pg, 256, POW_SMEM>>>(Th,  Th,  P2,  Th,  Th);
    pow_gemm<1><<<pg, 256, POW_SMEM>>>(P2,  Th,  S1h, Th,  P2);
    pow_gemm<0><<<pg, 256, POW_SMEM>>>(S1h, S1h, P2,  S1h, S1h);
    pow_gemm<1><<<pg, 256, POW_SMEM>>>(P2,  S1h, S2h, S1h, P2);

    // 5) chain: 16 matvecs (2 T, 1 S1, 13 S2)
    chain_kernel<<<B_, 512>>>(Th, S1h, S2h, str, cs);

    // 6) out = cov_sum[b][c] * x
    const long total4 = (long)B_ * C_ * M_ / 4;
    scale_kernel<<<(int)((total4 + 255) / 256), 256>>>(x, cs, out);

    (void)in_sizes; (void)n_in; (void)out_size;
}